// round 10
// baseline (speedup 1.0000x reference)
#include <cuda_runtime.h>
#include <cstdint>

#define N_NODES 50000
#define N_EDGES 800000
#define F_IN   128
#define F_HID  64
#define F_OUT  40
#define SCAN_B 1024
#define SCAN_NB ((N_NODES + SCAN_B - 1) / SCAN_B)   // 49

// ---------------- scratch (device globals: no allocation allowed) ----------
__device__ float g_h[N_NODES * 64];      // GEMM output h' (dinv-prescaled)
__device__ float g_z[N_NODES * 64];      // activation buffer
__device__ int   g_dege[N_NODES];        // edge-only degree (no self loop)
__device__ int   g_cursor[N_NODES];
__device__ int   g_rowstart[N_NODES];
__device__ int   g_csrc[N_EDGES];
__device__ int   g_bsum[SCAN_NB];
__device__ float g_dinv[N_NODES];

// ---------------- degree count ---------------------------------------------
__global__ void deg_count_k(const int* __restrict__ dst, int* __restrict__ dege) {
    int e = blockIdx.x * blockDim.x + threadIdx.x;
    if (e < N_EDGES) atomicAdd(&dege[dst[e]], 1);
}

// ---------------- fused scan + dinv + cursor init --------------------------
// two-level warp-shuffle scan (2 barriers); also computes dinv = rsqrt(deg+1)
// and zeroes the fill cursor.
__global__ __launch_bounds__(SCAN_B)
void scan1_k(const int* __restrict__ dege, int* __restrict__ rowstart,
             int* __restrict__ bsum, float* __restrict__ dinv,
             int* __restrict__ cursor)
{
    __shared__ int warpsum[32];
    const int t = threadIdx.x;
    const int lane = t & 31;
    const int wid = t >> 5;
    const int g = blockIdx.x * SCAN_B + t;

    int v = (g < N_NODES) ? dege[g] : 0;

    // inclusive warp scan
    int x = v;
    #pragma unroll
    for (int off = 1; off < 32; off <<= 1) {
        int y = __shfl_up_sync(0xFFFFFFFFu, x, off);
        if (lane >= off) x += y;
    }
    if (lane == 31) warpsum[wid] = x;
    __syncthreads();
    if (t < 32) {
        int w = warpsum[t];
        #pragma unroll
        for (int off = 1; off < 32; off <<= 1) {
            int y = __shfl_up_sync(0xFFFFFFFFu, w, off);
            if (t >= off) w += y;
        }
        warpsum[t] = w;
    }
    __syncthreads();

    int base = (wid > 0) ? warpsum[wid - 1] : 0;
    int incl = base + x;
    if (g < N_NODES) {
        rowstart[g] = incl - v;              // exclusive
        dinv[g] = rsqrtf((float)(v + 1));
        cursor[g] = 0;
    }
    if (t == SCAN_B - 1) bsum[blockIdx.x] = incl;
}

__global__ void scan2_k(int* __restrict__ bsum) {
    __shared__ int s[64];
    int t = threadIdx.x;
    int v = (t < SCAN_NB) ? bsum[t] : 0;
    s[t] = v;
    __syncthreads();
    #pragma unroll
    for (int off = 1; off < 64; off <<= 1) {
        int x = (t >= off) ? s[t - off] : 0;
        __syncthreads();
        s[t] += x;
        __syncthreads();
    }
    if (t < SCAN_NB) bsum[t] = s[t] - v;     // exclusive block offsets
}

__global__ __launch_bounds__(SCAN_B)
void scan3_k(int* __restrict__ rowstart, const int* __restrict__ bsum) {
    int t = threadIdx.x;
    int g = blockIdx.x * SCAN_B + t;
    if (g < N_NODES) rowstart[g] += bsum[blockIdx.x];
}

__global__ void fill_k(const int* __restrict__ src, const int* __restrict__ dst,
                       const int* __restrict__ rowstart, int* __restrict__ cursor,
                       int* __restrict__ csrc) {
    int e = blockIdx.x * blockDim.x + threadIdx.x;
    if (e < N_EDGES) {
        int d = dst[e];
        int pos = rowstart[d] + atomicAdd(&cursor[d], 1);
        csrc[pos] = src[e];
    }
}

// ---------------- GEMM: C = (A[N,M] @ W[M,K]) * dinv[row] ------------------
// BM=128, BN=64, BK=16, 256 threads, 8x4 micro-tile. A-tile stored transposed.
__global__ __launch_bounds__(256)
void gemm_scaled_k(const float* __restrict__ A, const float* __restrict__ W,
                   const float* __restrict__ dinv, float* __restrict__ C,
                   int M, int K)
{
    __shared__ float As[16][132];   // [k][row], padded against store conflicts
    __shared__ float Ws[16][64];    // [k][col]

    const int tid = threadIdx.x;
    const int tx  = tid & 15;            // col group: cols tx*4 .. +3
    const int ty  = tid >> 4;            // row group: rows ty*8 .. +7
    const int n0  = blockIdx.x * 128;

    const int aRow = tid >> 2;           // 0..63
    const int aCol = (tid & 3) << 2;     // 0,4,8,12
    const int wRow = tid >> 4;           // 0..15
    const int wCol = (tid & 15) << 2;    // 0..60

    float acc[8][4] = {};

    for (int k0 = 0; k0 < M; k0 += 16) {
        #pragma unroll
        for (int hh = 0; hh < 2; hh++) {
            int row = aRow + hh * 64;
            float4 av = make_float4(0.f, 0.f, 0.f, 0.f);
            if (n0 + row < N_NODES)
                av = *(const float4*)(A + (size_t)(n0 + row) * M + k0 + aCol);
            As[aCol + 0][row] = av.x;
            As[aCol + 1][row] = av.y;
            As[aCol + 2][row] = av.z;
            As[aCol + 3][row] = av.w;
        }
        float4 wv = make_float4(0.f, 0.f, 0.f, 0.f);
        if (wCol < K)
            wv = *(const float4*)(W + (size_t)(k0 + wRow) * K + wCol);
        *(float4*)&Ws[wRow][wCol] = wv;

        __syncthreads();

        #pragma unroll
        for (int k = 0; k < 16; k++) {
            float4 a0 = *(const float4*)&As[k][ty * 8];
            float4 a1 = *(const float4*)&As[k][ty * 8 + 4];
            float4 b  = *(const float4*)&Ws[k][tx * 4];
            float ar[8] = {a0.x, a0.y, a0.z, a0.w, a1.x, a1.y, a1.z, a1.w};
            #pragma unroll
            for (int i = 0; i < 8; i++) {
                acc[i][0] += ar[i] * b.x;
                acc[i][1] += ar[i] * b.y;
                acc[i][2] += ar[i] * b.z;
                acc[i][3] += ar[i] * b.w;
            }
        }
        __syncthreads();
    }

    const int colBase = tx << 2;
    if (colBase < K) {
        #pragma unroll
        for (int i = 0; i < 8; i++) {
            int row = n0 + ty * 8 + i;
            if (row < N_NODES) {
                float s = dinv[row];
                float4 v;
                v.x = acc[i][0] * s; v.y = acc[i][1] * s;
                v.z = acc[i][2] * s; v.w = acc[i][3] * s;
                *(float4*)(C + (size_t)row * K + colBase) = v;
            }
        }
    }
}

// ---------------- fused CSR aggregation + epilogue -------------------------
// z[d] = act( dinv[d] * ( h'[d] + sum_{s in N(d)} h'[s] ) + bias )
// 16 consecutive threads per node, each owns one float4 column slice.
// 4-way unrolled gather loop: 4 independent row gathers in flight per thread.
template<int F, bool RELU>
__global__ __launch_bounds__(256)
void agg_fused_k(const float* __restrict__ h, const int* __restrict__ rowstart,
                 const int* __restrict__ dege, const int* __restrict__ csrc,
                 const float* __restrict__ dinv, const float* __restrict__ bias,
                 float* __restrict__ z)
{
    unsigned t = blockIdx.x * blockDim.x + threadIdx.x;
    unsigned node = t >> 4;
    unsigned j = (t & 15) << 2;
    if (node >= N_NODES) return;
    const bool active = (j < F);

    float4 acc0 = make_float4(0.f, 0.f, 0.f, 0.f);
    float4 acc1 = make_float4(0.f, 0.f, 0.f, 0.f);
    if (active)
        acc0 = *(const float4*)(h + (size_t)node * F + j);   // self loop

    int i   = rowstart[node];
    int end = i + dege[node];

    for (; i + 4 <= end; i += 4) {
        int p0 = __ldg(&csrc[i + 0]);
        int p1 = __ldg(&csrc[i + 1]);
        int p2 = __ldg(&csrc[i + 2]);
        int p3 = __ldg(&csrc[i + 3]);
        if (active) {
            float4 v0 = __ldg((const float4*)(h + (size_t)p0 * F + j));
            float4 v1 = __ldg((const float4*)(h + (size_t)p1 * F + j));
            float4 v2 = __ldg((const float4*)(h + (size_t)p2 * F + j));
            float4 v3 = __ldg((const float4*)(h + (size_t)p3 * F + j));
            acc0.x += v0.x; acc0.y += v0.y; acc0.z += v0.z; acc0.w += v0.w;
            acc1.x += v1.x; acc1.y += v1.y; acc1.z += v1.z; acc1.w += v1.w;
            acc0.x += v2.x; acc0.y += v2.y; acc0.z += v2.z; acc0.w += v2.w;
            acc1.x += v3.x; acc1.y += v3.y; acc1.z += v3.z; acc1.w += v3.w;
        }
    }
    for (; i < end; i++) {
        int p = __ldg(&csrc[i]);
        if (active) {
            float4 v = __ldg((const float4*)(h + (size_t)p * F + j));
            acc0.x += v.x; acc0.y += v.y; acc0.z += v.z; acc0.w += v.w;
        }
    }

    if (active) {
        float sc = dinv[node];
        float4 b = *(const float4*)(bias + j);
        acc0.x += acc1.x; acc0.y += acc1.y; acc0.z += acc1.z; acc0.w += acc1.w;
        acc0.x = fmaf(acc0.x, sc, b.x);
        acc0.y = fmaf(acc0.y, sc, b.y);
        acc0.z = fmaf(acc0.z, sc, b.z);
        acc0.w = fmaf(acc0.w, sc, b.w);
        if (RELU) {
            acc0.x = fmaxf(acc0.x, 0.f); acc0.y = fmaxf(acc0.y, 0.f);
            acc0.z = fmaxf(acc0.z, 0.f); acc0.w = fmaxf(acc0.w, 0.f);
        }
        *(float4*)(z + (size_t)node * F + j) = acc0;
    }
}

// ---------------- launch ---------------------------------------------------
extern "C" void kernel_launch(void* const* d_in, const int* in_sizes, int n_in,
                              void* d_out, int out_size)
{
    const float* x  = (const float*)d_in[0];
    const int*   ei = (const int*)  d_in[1];
    const float* W1 = (const float*)d_in[2];
    const float* b1 = (const float*)d_in[3];
    const float* W2 = (const float*)d_in[4];
    const float* b2 = (const float*)d_in[5];
    const float* W3 = (const float*)d_in[6];
    const float* b3 = (const float*)d_in[7];
    float* out = (float*)d_out;

    const int* src = ei;              // edge_index[0]
    const int* dst = ei + N_EDGES;    // edge_index[1]

    float *h, *z, *dinv;
    int *dege, *cursor, *rowstart, *csrc, *bsum;
    cudaGetSymbolAddress((void**)&h,        g_h);
    cudaGetSymbolAddress((void**)&z,        g_z);
    cudaGetSymbolAddress((void**)&dinv,     g_dinv);
    cudaGetSymbolAddress((void**)&dege,     g_dege);
    cudaGetSymbolAddress((void**)&cursor,   g_cursor);
    cudaGetSymbolAddress((void**)&rowstart, g_rowstart);
    cudaGetSymbolAddress((void**)&csrc,     g_csrc);
    cudaGetSymbolAddress((void**)&bsum,     g_bsum);

    const int TPB = 256;
    const int edgeBlocks = (N_EDGES + TPB - 1) / TPB;
    const int gemmBlocks = (N_NODES + 127) / 128;
    const int aggBlocks  = ((unsigned)N_NODES * 16 + TPB - 1) / TPB;

    // ---- CSR build + normalization ----
    cudaMemsetAsync(dege, 0, N_NODES * sizeof(int));
    deg_count_k<<<edgeBlocks, TPB>>>(dst, dege);
    scan1_k    <<<SCAN_NB, SCAN_B>>>(dege, rowstart, bsum, dinv, cursor);
    scan2_k    <<<1, 64>>>(bsum);
    scan3_k    <<<SCAN_NB, SCAN_B>>>(rowstart, bsum);
    fill_k     <<<edgeBlocks, TPB>>>(src, dst, rowstart, cursor, csrc);

    // ---- layer 1: x[50000,128] @ W1[128,64] ----
    gemm_scaled_k<<<gemmBlocks, TPB>>>(x, W1, dinv, h, F_IN, F_HID);
    agg_fused_k<F_HID, true><<<aggBlocks, TPB>>>(h, rowstart, dege, csrc, dinv, b1, z);

    // ---- layer 2: z1 @ W2[64,64] ----
    gemm_scaled_k<<<gemmBlocks, TPB>>>(z, W2, dinv, h, F_HID, F_HID);
    agg_fused_k<F_HID, true><<<aggBlocks, TPB>>>(h, rowstart, dege, csrc, dinv, b2, z);

    // ---- layer 3: z2 @ W3[64,40] -> d_out ----
    gemm_scaled_k<<<gemmBlocks, TPB>>>(z, W3, dinv, h, F_HID, F_OUT);
    agg_fused_k<F_OUT, false><<<aggBlocks, TPB>>>(h, rowstart, dege, csrc, dinv, b3, out);
}

// round 15
// speedup vs baseline: 1.4976x; 1.4976x over previous
#include <cuda_runtime.h>
#include <cstdint>

#define N_NODES 50000
#define N_EDGES 800000
#define F_IN   128
#define F_HID  64
#define F_OUT  40
#define SCAN_B 1024
#define SCAN_NB ((N_NODES + SCAN_B - 1) / SCAN_B)   // 49

// ---------------- scratch (device globals: no allocation allowed) ----------
__device__ float g_h[N_NODES * 64];      // GEMM output h' (dinv-prescaled)
__device__ float g_z[N_NODES * 64];      // activation buffer
__device__ int   g_dege[N_NODES];        // edge-only degree (no self loop)
__device__ int   g_cursor[N_NODES];
__device__ int   g_rowstart[N_NODES];
__device__ int   g_csrc[N_EDGES];
__device__ int   g_bsum[SCAN_NB];
__device__ float g_dinv[N_NODES];

// ---------------- degree count ---------------------------------------------
__global__ void deg_count_k(const int* __restrict__ dst, int* __restrict__ dege) {
    int e = blockIdx.x * blockDim.x + threadIdx.x;
    if (e < N_EDGES) atomicAdd(&dege[dst[e]], 1);
}

// ---------------- fused scan + dinv + cursor init --------------------------
// two-level warp-shuffle scan (2 barriers); also computes dinv = rsqrt(deg+1)
// and zeroes the fill cursor.
__global__ __launch_bounds__(SCAN_B)
void scan1_k(const int* __restrict__ dege, int* __restrict__ rowstart,
             int* __restrict__ bsum, float* __restrict__ dinv,
             int* __restrict__ cursor)
{
    __shared__ int warpsum[32];
    const int t = threadIdx.x;
    const int lane = t & 31;
    const int wid = t >> 5;
    const int g = blockIdx.x * SCAN_B + t;

    int v = (g < N_NODES) ? dege[g] : 0;

    // inclusive warp scan
    int x = v;
    #pragma unroll
    for (int off = 1; off < 32; off <<= 1) {
        int y = __shfl_up_sync(0xFFFFFFFFu, x, off);
        if (lane >= off) x += y;
    }
    if (lane == 31) warpsum[wid] = x;
    __syncthreads();
    if (t < 32) {
        int w = warpsum[t];
        #pragma unroll
        for (int off = 1; off < 32; off <<= 1) {
            int y = __shfl_up_sync(0xFFFFFFFFu, w, off);
            if (t >= off) w += y;
        }
        warpsum[t] = w;
    }
    __syncthreads();

    int base = (wid > 0) ? warpsum[wid - 1] : 0;
    int incl = base + x;
    if (g < N_NODES) {
        rowstart[g] = incl - v;              // exclusive
        dinv[g] = rsqrtf((float)(v + 1));
        cursor[g] = 0;
    }
    if (t == SCAN_B - 1) bsum[blockIdx.x] = incl;
}

__global__ void scan2_k(int* __restrict__ bsum) {
    __shared__ int s[64];
    int t = threadIdx.x;
    int v = (t < SCAN_NB) ? bsum[t] : 0;
    s[t] = v;
    __syncthreads();
    #pragma unroll
    for (int off = 1; off < 64; off <<= 1) {
        int x = (t >= off) ? s[t - off] : 0;
        __syncthreads();
        s[t] += x;
        __syncthreads();
    }
    if (t < SCAN_NB) bsum[t] = s[t] - v;     // exclusive block offsets
}

__global__ __launch_bounds__(SCAN_B)
void scan3_k(int* __restrict__ rowstart, const int* __restrict__ bsum) {
    int t = threadIdx.x;
    int g = blockIdx.x * SCAN_B + t;
    if (g < N_NODES) rowstart[g] += bsum[blockIdx.x];
}

__global__ void fill_k(const int* __restrict__ src, const int* __restrict__ dst,
                       const int* __restrict__ rowstart, int* __restrict__ cursor,
                       int* __restrict__ csrc) {
    int e = blockIdx.x * blockDim.x + threadIdx.x;
    if (e < N_EDGES) {
        int d = dst[e];
        int pos = rowstart[d] + atomicAdd(&cursor[d], 1);
        csrc[pos] = src[e];
    }
}

// ---------------- GEMM: C = (A[N,M] @ W[M,K]) * dinv[row] ------------------
// BM=128, BN=64, BK=16, 256 threads, 8x4 micro-tile. A-tile stored transposed.
__global__ __launch_bounds__(256)
void gemm_scaled_k(const float* __restrict__ A, const float* __restrict__ W,
                   const float* __restrict__ dinv, float* __restrict__ C,
                   int M, int K)
{
    __shared__ float As[16][132];   // [k][row], padded against store conflicts
    __shared__ float Ws[16][64];    // [k][col]

    const int tid = threadIdx.x;
    const int tx  = tid & 15;            // col group: cols tx*4 .. +3
    const int ty  = tid >> 4;            // row group: rows ty*8 .. +7
    const int n0  = blockIdx.x * 128;

    const int aRow = tid >> 2;           // 0..63
    const int aCol = (tid & 3) << 2;     // 0,4,8,12
    const int wRow = tid >> 4;           // 0..15
    const int wCol = (tid & 15) << 2;    // 0..60

    float acc[8][4] = {};

    for (int k0 = 0; k0 < M; k0 += 16) {
        #pragma unroll
        for (int hh = 0; hh < 2; hh++) {
            int row = aRow + hh * 64;
            float4 av = make_float4(0.f, 0.f, 0.f, 0.f);
            if (n0 + row < N_NODES)
                av = *(const float4*)(A + (size_t)(n0 + row) * M + k0 + aCol);
            As[aCol + 0][row] = av.x;
            As[aCol + 1][row] = av.y;
            As[aCol + 2][row] = av.z;
            As[aCol + 3][row] = av.w;
        }
        float4 wv = make_float4(0.f, 0.f, 0.f, 0.f);
        if (wCol < K)
            wv = *(const float4*)(W + (size_t)(k0 + wRow) * K + wCol);
        *(float4*)&Ws[wRow][wCol] = wv;

        __syncthreads();

        #pragma unroll
        for (int k = 0; k < 16; k++) {
            float4 a0 = *(const float4*)&As[k][ty * 8];
            float4 a1 = *(const float4*)&As[k][ty * 8 + 4];
            float4 b  = *(const float4*)&Ws[k][tx * 4];
            float ar[8] = {a0.x, a0.y, a0.z, a0.w, a1.x, a1.y, a1.z, a1.w};
            #pragma unroll
            for (int i = 0; i < 8; i++) {
                acc[i][0] += ar[i] * b.x;
                acc[i][1] += ar[i] * b.y;
                acc[i][2] += ar[i] * b.z;
                acc[i][3] += ar[i] * b.w;
            }
        }
        __syncthreads();
    }

    const int colBase = tx << 2;
    if (colBase < K) {
        #pragma unroll
        for (int i = 0; i < 8; i++) {
            int row = n0 + ty * 8 + i;
            if (row < N_NODES) {
                float s = dinv[row];
                float4 v;
                v.x = acc[i][0] * s; v.y = acc[i][1] * s;
                v.z = acc[i][2] * s; v.w = acc[i][3] * s;
                *(float4*)(C + (size_t)row * K + colBase) = v;
            }
        }
    }
}

// ---------------- fused CSR aggregation + epilogue -------------------------
// z[d] = act( dinv[d] * ( h'[d] + sum_{s in N(d)} h'[s] ) + bias )
// 16 consecutive threads per node, each owns one float4 column slice.
// 4-way unrolled gather loop: 4 independent row gathers in flight per thread.
template<int F, bool RELU>
__global__ __launch_bounds__(256)
void agg_fused_k(const float* __restrict__ h, const int* __restrict__ rowstart,
                 const int* __restrict__ dege, const int* __restrict__ csrc,
                 const float* __restrict__ dinv, const float* __restrict__ bias,
                 float* __restrict__ z)
{
    unsigned t = blockIdx.x * blockDim.x + threadIdx.x;
    unsigned node = t >> 4;
    unsigned j = (t & 15) << 2;
    if (node >= N_NODES) return;
    const bool active = (j < F);

    float4 acc0 = make_float4(0.f, 0.f, 0.f, 0.f);
    float4 acc1 = make_float4(0.f, 0.f, 0.f, 0.f);
    if (active)
        acc0 = *(const float4*)(h + (size_t)node * F + j);   // self loop

    int i   = rowstart[node];
    int end = i + dege[node];

    for (; i + 4 <= end; i += 4) {
        int p0 = __ldg(&csrc[i + 0]);
        int p1 = __ldg(&csrc[i + 1]);
        int p2 = __ldg(&csrc[i + 2]);
        int p3 = __ldg(&csrc[i + 3]);
        if (active) {
            float4 v0 = __ldg((const float4*)(h + (size_t)p0 * F + j));
            float4 v1 = __ldg((const float4*)(h + (size_t)p1 * F + j));
            float4 v2 = __ldg((const float4*)(h + (size_t)p2 * F + j));
            float4 v3 = __ldg((const float4*)(h + (size_t)p3 * F + j));
            acc0.x += v0.x; acc0.y += v0.y; acc0.z += v0.z; acc0.w += v0.w;
            acc1.x += v1.x; acc1.y += v1.y; acc1.z += v1.z; acc1.w += v1.w;
            acc0.x += v2.x; acc0.y += v2.y; acc0.z += v2.z; acc0.w += v2.w;
            acc1.x += v3.x; acc1.y += v3.y; acc1.z += v3.z; acc1.w += v3.w;
        }
    }
    for (; i < end; i++) {
        int p = __ldg(&csrc[i]);
        if (active) {
            float4 v = __ldg((const float4*)(h + (size_t)p * F + j));
            acc0.x += v.x; acc0.y += v.y; acc0.z += v.z; acc0.w += v.w;
        }
    }

    if (active) {
        float sc = dinv[node];
        float4 b = *(const float4*)(bias + j);
        acc0.x += acc1.x; acc0.y += acc1.y; acc0.z += acc1.z; acc0.w += acc1.w;
        acc0.x = fmaf(acc0.x, sc, b.x);
        acc0.y = fmaf(acc0.y, sc, b.y);
        acc0.z = fmaf(acc0.z, sc, b.z);
        acc0.w = fmaf(acc0.w, sc, b.w);
        if (RELU) {
            acc0.x = fmaxf(acc0.x, 0.f); acc0.y = fmaxf(acc0.y, 0.f);
            acc0.z = fmaxf(acc0.z, 0.f); acc0.w = fmaxf(acc0.w, 0.f);
        }
        *(float4*)(z + (size_t)node * F + j) = acc0;
    }
}

// ---------------- launch ---------------------------------------------------
extern "C" void kernel_launch(void* const* d_in, const int* in_sizes, int n_in,
                              void* d_out, int out_size)
{
    const float* x  = (const float*)d_in[0];
    const int*   ei = (const int*)  d_in[1];
    const float* W1 = (const float*)d_in[2];
    const float* b1 = (const float*)d_in[3];
    const float* W2 = (const float*)d_in[4];
    const float* b2 = (const float*)d_in[5];
    const float* W3 = (const float*)d_in[6];
    const float* b3 = (const float*)d_in[7];
    float* out = (float*)d_out;

    const int* src = ei;              // edge_index[0]
    const int* dst = ei + N_EDGES;    // edge_index[1]

    float *h, *z, *dinv;
    int *dege, *cursor, *rowstart, *csrc, *bsum;
    cudaGetSymbolAddress((void**)&h,        g_h);
    cudaGetSymbolAddress((void**)&z,        g_z);
    cudaGetSymbolAddress((void**)&dinv,     g_dinv);
    cudaGetSymbolAddress((void**)&dege,     g_dege);
    cudaGetSymbolAddress((void**)&cursor,   g_cursor);
    cudaGetSymbolAddress((void**)&rowstart, g_rowstart);
    cudaGetSymbolAddress((void**)&csrc,     g_csrc);
    cudaGetSymbolAddress((void**)&bsum,     g_bsum);

    const int TPB = 256;
    const int edgeBlocks = (N_EDGES + TPB - 1) / TPB;
    const int gemmBlocks = (N_NODES + 127) / 128;
    const int aggBlocks  = ((unsigned)N_NODES * 16 + TPB - 1) / TPB;

    // ---- CSR build + normalization ----
    cudaMemsetAsync(dege, 0, N_NODES * sizeof(int));
    deg_count_k<<<edgeBlocks, TPB>>>(dst, dege);
    scan1_k    <<<SCAN_NB, SCAN_B>>>(dege, rowstart, bsum, dinv, cursor);
    scan2_k    <<<1, 64>>>(bsum);
    scan3_k    <<<SCAN_NB, SCAN_B>>>(rowstart, bsum);
    fill_k     <<<edgeBlocks, TPB>>>(src, dst, rowstart, cursor, csrc);

    // ---- layer 1: x[50000,128] @ W1[128,64] ----
    gemm_scaled_k<<<gemmBlocks, TPB>>>(x, W1, dinv, h, F_IN, F_HID);
    agg_fused_k<F_HID, true><<<aggBlocks, TPB>>>(h, rowstart, dege, csrc, dinv, b1, z);

    // ---- layer 2: z1 @ W2[64,64] ----
    gemm_scaled_k<<<gemmBlocks, TPB>>>(z, W2, dinv, h, F_HID, F_HID);
    agg_fused_k<F_HID, true><<<aggBlocks, TPB>>>(h, rowstart, dege, csrc, dinv, b2, z);

    // ---- layer 3: z2 @ W3[64,40] -> d_out ----
    gemm_scaled_k<<<gemmBlocks, TPB>>>(z, W3, dinv, h, F_HID, F_OUT);
    agg_fused_k<F_OUT, false><<<aggBlocks, TPB>>>(h, rowstart, dege, csrc, dinv, b3, out);
}

// round 16
// speedup vs baseline: 1.5601x; 1.0418x over previous
#include <cuda_runtime.h>
#include <cuda_fp16.h>
#include <cstdint>

#define N_NODES 50000
#define N_EDGES 800000
#define F_IN   128
#define F_HID  64
#define F_OUT  40
#define SCAN_B   1024
#define SCAN_ELE 2048                                  // 2 elems / thread
#define SCAN_NB ((N_NODES + SCAN_ELE - 1) / SCAN_ELE)  // 25

// ---------------- scratch (device globals: no allocation allowed) ----------
__device__ __half g_h[N_NODES * 64];     // GEMM output h' (dinv-prescaled, fp16)
__device__ float  g_z[N_NODES * 64];     // activation buffer (fp32)
__device__ int    g_dege[N_NODES];       // edge-only degree (no self loop)
__device__ int    g_cursor[N_NODES];
__device__ int    g_rowstart[N_NODES];   // block-local exclusive prefix
__device__ int    g_csrc[N_EDGES];
__device__ int    g_bsum[SCAN_NB];       // per-block totals (un-scanned)
__device__ float  g_dinv[N_NODES];

// ---------------- degree count ---------------------------------------------
__global__ void deg_count_k(const int* __restrict__ dst, int* __restrict__ dege) {
    int e = blockIdx.x * blockDim.x + threadIdx.x;
    if (e < N_EDGES) atomicAdd(&dege[dst[e]], 1);
}

// ---------------- fused scan + dinv + cursor init (2 elems/thread) ---------
__global__ __launch_bounds__(SCAN_B)
void scan1_k(const int* __restrict__ dege, int* __restrict__ rowstart,
             int* __restrict__ bsum, float* __restrict__ dinv,
             int* __restrict__ cursor)
{
    __shared__ int warpsum[32];
    const int t = threadIdx.x;
    const int lane = t & 31;
    const int wid = t >> 5;
    const int g0 = blockIdx.x * SCAN_ELE + 2 * t;

    int v0 = (g0     < N_NODES) ? dege[g0]     : 0;
    int v1 = (g0 + 1 < N_NODES) ? dege[g0 + 1] : 0;
    int pair = v0 + v1;

    // inclusive warp scan over pair-sums
    int x = pair;
    #pragma unroll
    for (int off = 1; off < 32; off <<= 1) {
        int y = __shfl_up_sync(0xFFFFFFFFu, x, off);
        if (lane >= off) x += y;
    }
    if (lane == 31) warpsum[wid] = x;
    __syncthreads();
    if (t < 32) {
        int w = warpsum[t];
        #pragma unroll
        for (int off = 1; off < 32; off <<= 1) {
            int y = __shfl_up_sync(0xFFFFFFFFu, w, off);
            if (t >= off) w += y;
        }
        warpsum[t] = w;
    }
    __syncthreads();

    int base = (wid > 0) ? warpsum[wid - 1] : 0;
    int incl = base + x;
    int excl = incl - pair;
    if (g0 < N_NODES) {
        rowstart[g0] = excl;
        dinv[g0] = rsqrtf((float)(v0 + 1));
        cursor[g0] = 0;
    }
    if (g0 + 1 < N_NODES) {
        rowstart[g0 + 1] = excl + v0;
        dinv[g0 + 1] = rsqrtf((float)(v1 + 1));
        cursor[g0 + 1] = 0;
    }
    if (t == SCAN_B - 1) bsum[blockIdx.x] = incl;   // block total
}

// 25-element exclusive mini-scan of bsum into shared (warp 0), barrier incl.
__device__ __forceinline__ void mini_scan_bsum(const int* __restrict__ bsum,
                                               int* __restrict__ sb) {
    if (threadIdx.x < 32) {
        int v = (threadIdx.x < SCAN_NB) ? bsum[threadIdx.x] : 0;
        int x = v;
        #pragma unroll
        for (int off = 1; off < 32; off <<= 1) {
            int y = __shfl_up_sync(0xFFFFFFFFu, x, off);
            if (threadIdx.x >= off) x += y;
        }
        sb[threadIdx.x] = x - v;     // exclusive
    }
    __syncthreads();
}

__global__ __launch_bounds__(256)
void fill_k(const int* __restrict__ src, const int* __restrict__ dst,
            const int* __restrict__ rowstart, const int* __restrict__ bsum,
            int* __restrict__ cursor, int* __restrict__ csrc) {
    __shared__ int sb[32];
    mini_scan_bsum(bsum, sb);
    int e = blockIdx.x * blockDim.x + threadIdx.x;
    if (e < N_EDGES) {
        int d = dst[e];
        int pos = rowstart[d] + sb[d >> 11] + atomicAdd(&cursor[d], 1);
        csrc[pos] = src[e];
    }
}

// ---------------- GEMM: C = half( (A[N,M] @ W[M,K]) * dinv[row] ) ----------
// BM=128, BN=64, BK=16, 256 threads, 8x4 micro-tile. A-tile stored transposed.
struct alignas(8) half4 { __half2 a, b; };

__global__ __launch_bounds__(256)
void gemm_scaled_k(const float* __restrict__ A, const float* __restrict__ W,
                   const float* __restrict__ dinv, __half* __restrict__ C,
                   int M, int K)
{
    __shared__ float As[16][132];   // [k][row], padded against store conflicts
    __shared__ float Ws[16][64];    // [k][col]

    const int tid = threadIdx.x;
    const int tx  = tid & 15;            // col group: cols tx*4 .. +3
    const int ty  = tid >> 4;            // row group: rows ty*8 .. +7
    const int n0  = blockIdx.x * 128;

    const int aRow = tid >> 2;           // 0..63
    const int aCol = (tid & 3) << 2;     // 0,4,8,12
    const int wRow = tid >> 4;           // 0..15
    const int wCol = (tid & 15) << 2;    // 0..60

    float acc[8][4] = {};

    for (int k0 = 0; k0 < M; k0 += 16) {
        #pragma unroll
        for (int hh = 0; hh < 2; hh++) {
            int row = aRow + hh * 64;
            float4 av = make_float4(0.f, 0.f, 0.f, 0.f);
            if (n0 + row < N_NODES)
                av = *(const float4*)(A + (size_t)(n0 + row) * M + k0 + aCol);
            As[aCol + 0][row] = av.x;
            As[aCol + 1][row] = av.y;
            As[aCol + 2][row] = av.z;
            As[aCol + 3][row] = av.w;
        }
        float4 wv = make_float4(0.f, 0.f, 0.f, 0.f);
        if (wCol < K)
            wv = *(const float4*)(W + (size_t)(k0 + wRow) * K + wCol);
        *(float4*)&Ws[wRow][wCol] = wv;

        __syncthreads();

        #pragma unroll
        for (int k = 0; k < 16; k++) {
            float4 a0 = *(const float4*)&As[k][ty * 8];
            float4 a1 = *(const float4*)&As[k][ty * 8 + 4];
            float4 b  = *(const float4*)&Ws[k][tx * 4];
            float ar[8] = {a0.x, a0.y, a0.z, a0.w, a1.x, a1.y, a1.z, a1.w};
            #pragma unroll
            for (int i = 0; i < 8; i++) {
                acc[i][0] += ar[i] * b.x;
                acc[i][1] += ar[i] * b.y;
                acc[i][2] += ar[i] * b.z;
                acc[i][3] += ar[i] * b.w;
            }
        }
        __syncthreads();
    }

    const int colBase = tx << 2;
    if (colBase < K) {
        #pragma unroll
        for (int i = 0; i < 8; i++) {
            int row = n0 + ty * 8 + i;
            if (row < N_NODES) {
                float s = dinv[row];
                half4 hv;
                hv.a = __floats2half2_rn(acc[i][0] * s, acc[i][1] * s);
                hv.b = __floats2half2_rn(acc[i][2] * s, acc[i][3] * s);
                *(half4*)(C + (size_t)row * K + colBase) = hv;
            }
        }
    }
}

// ---------------- fused CSR aggregation + epilogue (fp16 gather) -----------
// z[d] = act( dinv[d] * ( h'[d] + sum_{s in N(d)} h'[s] ) + bias ), z fp32.
// TPN threads per node; each thread owns 8 columns (16B half gather).
__device__ __forceinline__ void add8(float acc[8], uint4 raw) {
    float2 f0 = __half22float2(*reinterpret_cast<__half2*>(&raw.x));
    float2 f1 = __half22float2(*reinterpret_cast<__half2*>(&raw.y));
    float2 f2 = __half22float2(*reinterpret_cast<__half2*>(&raw.z));
    float2 f3 = __half22float2(*reinterpret_cast<__half2*>(&raw.w));
    acc[0] += f0.x; acc[1] += f0.y;
    acc[2] += f1.x; acc[3] += f1.y;
    acc[4] += f2.x; acc[5] += f2.y;
    acc[6] += f3.x; acc[7] += f3.y;
}

template<int F, int TPN, bool RELU>
__global__ __launch_bounds__(256)
void agg_fused_k(const __half* __restrict__ h, const int* __restrict__ rowstart,
                 const int* __restrict__ bsum, const int* __restrict__ dege,
                 const int* __restrict__ csrc, const float* __restrict__ dinv,
                 const float* __restrict__ bias, float* __restrict__ z)
{
    __shared__ int sb[32];
    mini_scan_bsum(bsum, sb);

    unsigned t = blockIdx.x * blockDim.x + threadIdx.x;
    unsigned node = t / TPN;
    unsigned col = (t - node * TPN) * 8;
    if (node >= N_NODES) return;

    float acc[8] = {};
    add8(acc, __ldg((const uint4*)(h + (size_t)node * F + col)));   // self loop

    int i   = rowstart[node] + sb[node >> 11];
    int end = i + dege[node];

    for (; i + 4 <= end; i += 4) {
        int p0 = __ldg(&csrc[i + 0]);
        int p1 = __ldg(&csrc[i + 1]);
        int p2 = __ldg(&csrc[i + 2]);
        int p3 = __ldg(&csrc[i + 3]);
        uint4 r0 = __ldg((const uint4*)(h + (size_t)p0 * F + col));
        uint4 r1 = __ldg((const uint4*)(h + (size_t)p1 * F + col));
        uint4 r2 = __ldg((const uint4*)(h + (size_t)p2 * F + col));
        uint4 r3 = __ldg((const uint4*)(h + (size_t)p3 * F + col));
        add8(acc, r0); add8(acc, r1); add8(acc, r2); add8(acc, r3);
    }
    for (; i < end; i++) {
        int p = __ldg(&csrc[i]);
        add8(acc, __ldg((const uint4*)(h + (size_t)p * F + col)));
    }

    float sc = dinv[node];
    float4 b0 = *(const float4*)(bias + col);
    float4 b1 = *(const float4*)(bias + col + 4);
    float4 r0, r1;
    r0.x = fmaf(acc[0], sc, b0.x); r0.y = fmaf(acc[1], sc, b0.y);
    r0.z = fmaf(acc[2], sc, b0.z); r0.w = fmaf(acc[3], sc, b0.w);
    r1.x = fmaf(acc[4], sc, b1.x); r1.y = fmaf(acc[5], sc, b1.y);
    r1.z = fmaf(acc[6], sc, b1.z); r1.w = fmaf(acc[7], sc, b1.w);
    if (RELU) {
        r0.x = fmaxf(r0.x, 0.f); r0.y = fmaxf(r0.y, 0.f);
        r0.z = fmaxf(r0.z, 0.f); r0.w = fmaxf(r0.w, 0.f);
        r1.x = fmaxf(r1.x, 0.f); r1.y = fmaxf(r1.y, 0.f);
        r1.z = fmaxf(r1.z, 0.f); r1.w = fmaxf(r1.w, 0.f);
    }
    *(float4*)(z + (size_t)node * F + col)     = r0;
    *(float4*)(z + (size_t)node * F + col + 4) = r1;
}

// ---------------- launch ---------------------------------------------------
extern "C" void kernel_launch(void* const* d_in, const int* in_sizes, int n_in,
                              void* d_out, int out_size)
{
    const float* x  = (const float*)d_in[0];
    const int*   ei = (const int*)  d_in[1];
    const float* W1 = (const float*)d_in[2];
    const float* b1 = (const float*)d_in[3];
    const float* W2 = (const float*)d_in[4];
    const float* b2 = (const float*)d_in[5];
    const float* W3 = (const float*)d_in[6];
    const float* b3 = (const float*)d_in[7];
    float* out = (float*)d_out;

    const int* src = ei;              // edge_index[0]
    const int* dst = ei + N_EDGES;    // edge_index[1]

    __half* h;
    float *z, *dinv;
    int *dege, *cursor, *rowstart, *csrc, *bsum;
    cudaGetSymbolAddress((void**)&h,        g_h);
    cudaGetSymbolAddress((void**)&z,        g_z);
    cudaGetSymbolAddress((void**)&dinv,     g_dinv);
    cudaGetSymbolAddress((void**)&dege,     g_dege);
    cudaGetSymbolAddress((void**)&cursor,   g_cursor);
    cudaGetSymbolAddress((void**)&rowstart, g_rowstart);
    cudaGetSymbolAddress((void**)&csrc,     g_csrc);
    cudaGetSymbolAddress((void**)&bsum,     g_bsum);

    const int TPB = 256;
    const int edgeBlocks = (N_EDGES + TPB - 1) / TPB;
    const int gemmBlocks = (N_NODES + 127) / 128;
    const int agg64Blocks = ((unsigned)N_NODES * 8 + TPB - 1) / TPB;   // TPN=8
    const int agg40Blocks = ((unsigned)N_NODES * 5 + TPB - 1) / TPB;   // TPN=5

    // ---- CSR build + normalization (4 launches) ----
    cudaMemsetAsync(dege, 0, N_NODES * sizeof(int));
    deg_count_k<<<edgeBlocks, TPB>>>(dst, dege);
    scan1_k    <<<SCAN_NB, SCAN_B>>>(dege, rowstart, bsum, dinv, cursor);
    fill_k     <<<edgeBlocks, TPB>>>(src, dst, rowstart, bsum, cursor, csrc);

    // ---- layer 1: x[50000,128] @ W1[128,64] ----
    gemm_scaled_k<<<gemmBlocks, TPB>>>(x, W1, dinv, h, F_IN, F_HID);
    agg_fused_k<F_HID, 8, true><<<agg64Blocks, TPB>>>(h, rowstart, bsum, dege, csrc, dinv, b1, z);

    // ---- layer 2: z1 @ W2[64,64] ----
    gemm_scaled_k<<<gemmBlocks, TPB>>>(z, W2, dinv, h, F_HID, F_HID);
    agg_fused_k<F_HID, 8, true><<<agg64Blocks, TPB>>>(h, rowstart, bsum, dege, csrc, dinv, b2, z);

    // ---- layer 3: z2 @ W3[64,40] -> d_out ----
    gemm_scaled_k<<<gemmBlocks, TPB>>>(z, W3, dinv, h, F_HID, F_OUT);
    agg_fused_k<F_OUT, 5, false><<<agg40Blocks, TPB>>>(h, rowstart, bsum, dege, csrc, dinv, b3, out);
}

// round 17
// speedup vs baseline: 2.0576x; 1.3189x over previous
#include <cuda_runtime.h>
#include <cuda_fp16.h>
#include <cstdint>

#define N_NODES 50000
#define N_EDGES 800000
#define F_IN   128
#define F_HID  64
#define F_OUT  40
#define SCAN_B   1024
#define SCAN_ELE 2048                                  // 2 elems / thread
#define SCAN_NB ((N_NODES + SCAN_ELE - 1) / SCAN_ELE)  // 25

// ---------------- scratch (device globals: no allocation allowed) ----------
__device__ __half g_h[N_NODES * 64];     // GEMM output h' (dinv-prescaled, fp16)
__device__ float  g_z[N_NODES * 64];     // activation buffer (fp32)
__device__ int    g_dege[N_NODES];       // edge-only degree (no self loop)
__device__ int    g_cursor[N_NODES];
__device__ int    g_rowstart[N_NODES];   // block-local exclusive prefix
__device__ int    g_csrc[N_EDGES];
__device__ int    g_bsum[SCAN_NB];       // per-block totals (un-scanned)
__device__ float  g_dinv[N_NODES];

// ---------------- degree count ---------------------------------------------
__global__ void deg_count_k(const int* __restrict__ dst, int* __restrict__ dege) {
    int e = blockIdx.x * blockDim.x + threadIdx.x;
    if (e < N_EDGES) atomicAdd(&dege[dst[e]], 1);
}

// ---------------- fused scan + dinv + cursor init (2 elems/thread) ---------
__global__ __launch_bounds__(SCAN_B)
void scan1_k(const int* __restrict__ dege, int* __restrict__ rowstart,
             int* __restrict__ bsum, float* __restrict__ dinv,
             int* __restrict__ cursor)
{
    __shared__ int warpsum[32];
    const int t = threadIdx.x;
    const int lane = t & 31;
    const int wid = t >> 5;
    const int g0 = blockIdx.x * SCAN_ELE + 2 * t;

    int v0 = (g0     < N_NODES) ? dege[g0]     : 0;
    int v1 = (g0 + 1 < N_NODES) ? dege[g0 + 1] : 0;
    int pair = v0 + v1;

    int x = pair;
    #pragma unroll
    for (int off = 1; off < 32; off <<= 1) {
        int y = __shfl_up_sync(0xFFFFFFFFu, x, off);
        if (lane >= off) x += y;
    }
    if (lane == 31) warpsum[wid] = x;
    __syncthreads();
    if (t < 32) {
        int w = warpsum[t];
        #pragma unroll
        for (int off = 1; off < 32; off <<= 1) {
            int y = __shfl_up_sync(0xFFFFFFFFu, w, off);
            if (t >= off) w += y;
        }
        warpsum[t] = w;
    }
    __syncthreads();

    int base = (wid > 0) ? warpsum[wid - 1] : 0;
    int incl = base + x;
    int excl = incl - pair;
    if (g0 < N_NODES) {
        rowstart[g0] = excl;
        dinv[g0] = rsqrtf((float)(v0 + 1));
        cursor[g0] = 0;
    }
    if (g0 + 1 < N_NODES) {
        rowstart[g0 + 1] = excl + v0;
        dinv[g0 + 1] = rsqrtf((float)(v1 + 1));
        cursor[g0 + 1] = 0;
    }
    if (t == SCAN_B - 1) bsum[blockIdx.x] = incl;   // block total
}

// 25-element exclusive mini-scan of bsum into shared (warp 0), barrier incl.
__device__ __forceinline__ void mini_scan_bsum(const int* __restrict__ bsum,
                                               int* __restrict__ sb) {
    if (threadIdx.x < 32) {
        int v = (threadIdx.x < SCAN_NB) ? bsum[threadIdx.x] : 0;
        int x = v;
        #pragma unroll
        for (int off = 1; off < 32; off <<= 1) {
            int y = __shfl_up_sync(0xFFFFFFFFu, x, off);
            if (threadIdx.x >= off) x += y;
        }
        sb[threadIdx.x] = x - v;     // exclusive
    }
    __syncthreads();
}

__global__ __launch_bounds__(256)
void fill_k(const int* __restrict__ src, const int* __restrict__ dst,
            const int* __restrict__ rowstart, const int* __restrict__ bsum,
            int* __restrict__ cursor, int* __restrict__ csrc) {
    __shared__ int sb[32];
    mini_scan_bsum(bsum, sb);
    int e = blockIdx.x * blockDim.x + threadIdx.x;
    if (e < N_EDGES) {
        int d = dst[e];
        int pos = rowstart[d] + sb[d >> 11] + atomicAdd(&cursor[d], 1);
        csrc[pos] = src[e];
    }
}

// ---------------- HMMA GEMM: C = half( (A[N,M] @ W[M,K]) * dinv[row] ) -----
// BM=128, BN=64 (covers K<=64), 256 threads = 8 warps, warp tile 32x32.
// A fp32->fp16 in smem, W fp32->fp16 once per block, fp32 accumulate.
__device__ __forceinline__ void ldsm_x4(uint32_t& r0, uint32_t& r1,
                                        uint32_t& r2, uint32_t& r3, uint32_t a) {
    asm volatile("ldmatrix.sync.aligned.m8n8.x4.shared.b16 {%0,%1,%2,%3}, [%4];"
                 : "=r"(r0), "=r"(r1), "=r"(r2), "=r"(r3) : "r"(a));
}
__device__ __forceinline__ void ldsm_x2t(uint32_t& r0, uint32_t& r1, uint32_t a) {
    asm volatile("ldmatrix.sync.aligned.m8n8.x2.trans.shared.b16 {%0,%1}, [%2];"
                 : "=r"(r0), "=r"(r1) : "r"(a));
}
__device__ __forceinline__ void mma16816(float* d, const uint32_t* a,
                                         const uint32_t* b) {
    asm volatile(
        "mma.sync.aligned.m16n8k16.row.col.f32.f16.f16.f32 "
        "{%0,%1,%2,%3}, {%4,%5,%6,%7}, {%8,%9}, {%0,%1,%2,%3};"
        : "+f"(d[0]), "+f"(d[1]), "+f"(d[2]), "+f"(d[3])
        : "r"(a[0]), "r"(a[1]), "r"(a[2]), "r"(a[3]), "r"(b[0]), "r"(b[1]));
}

__global__ __launch_bounds__(256)
void gemm_hmma_k(const float* __restrict__ A, const float* __restrict__ W,
                 const float* __restrict__ dinv, __half* __restrict__ C,
                 int M, int K)
{
    __shared__ __half As[128][40];   // 128 rows x 32 k  (+8 pad, stride 80B)
    __shared__ __half Ws[128][72];   // M rows x 64 n    (+8 pad, stride 144B)

    const int tid  = threadIdx.x;
    const int lane = tid & 31;
    const int w    = tid >> 5;
    const int n0   = blockIdx.x * 128;

    const int mrow = (w >> 1) * 32;       // warp row base in tile
    const int ncol = (w & 1) * 32;        // warp col base

    // ---- load W (whole) into smem, fp16, zero-padded to 64 cols ----
    for (int idx = tid; idx < M * 64; idx += 256) {
        int k = idx >> 6, n = idx & 63;
        float wv = (n < K) ? W[k * K + n] : 0.f;
        Ws[k][n] = __float2half_rn(wv);
    }

    const uint32_t asBase = (uint32_t)__cvta_generic_to_shared(&As[0][0]);
    const uint32_t wsBase = (uint32_t)__cvta_generic_to_shared(&Ws[0][0]);

    float acc[2][4][4] = {};

    const int arow = tid >> 3;            // 0..31
    const int afq  = tid & 7;             // float4 index within 32 cols

    for (int kt = 0; kt < M; kt += 32) {
        // ---- load A tile [128 x 32] fp32 -> fp16 smem ----
        #pragma unroll
        for (int p = 0; p < 4; p++) {
            int row = arow + p * 32;
            float4 f = make_float4(0.f, 0.f, 0.f, 0.f);
            if (n0 + row < N_NODES)
                f = *(const float4*)(A + (size_t)(n0 + row) * M + kt + afq * 4);
            __half2 h0 = __floats2half2_rn(f.x, f.y);
            __half2 h1 = __floats2half2_rn(f.z, f.w);
            *(uint2*)&As[row][afq * 4] =
                make_uint2(*(uint32_t*)&h0, *(uint32_t*)&h1);
        }
        __syncthreads();

        #pragma unroll
        for (int ks = 0; ks < 2; ks++) {
            const int kb = ks * 16;
            uint32_t afr[2][4];
            #pragma unroll
            for (int mt = 0; mt < 2; mt++) {
                uint32_t addr = asBase +
                    ((mrow + mt * 16 + (lane & 15)) * 40 + kb + ((lane >> 4) << 3)) * 2;
                ldsm_x4(afr[mt][0], afr[mt][1], afr[mt][2], afr[mt][3], addr);
            }
            uint32_t bfr[4][2];
            #pragma unroll
            for (int nt = 0; nt < 4; nt++) {
                uint32_t addr = wsBase +
                    ((kt + kb + (lane & 15)) * 72 + ncol + nt * 8) * 2;
                ldsm_x2t(bfr[nt][0], bfr[nt][1], addr);
            }
            #pragma unroll
            for (int mt = 0; mt < 2; mt++)
                #pragma unroll
                for (int nt = 0; nt < 4; nt++)
                    mma16816(acc[mt][nt], afr[mt], bfr[nt]);
        }
        __syncthreads();
    }

    // ---- epilogue: dinv scale -> fp16 store ----
    const int r  = lane >> 2;
    const int c2 = (lane & 3) * 2;
    #pragma unroll
    for (int mt = 0; mt < 2; mt++) {
        int row0 = n0 + mrow + mt * 16 + r;
        int row1 = row0 + 8;
        float s0 = (row0 < N_NODES) ? dinv[row0] : 0.f;
        float s1 = (row1 < N_NODES) ? dinv[row1] : 0.f;
        #pragma unroll
        for (int nt = 0; nt < 4; nt++) {
            int col = ncol + nt * 8 + c2;
            if (col < K) {
                if (row0 < N_NODES) {
                    __half2 hv = __floats2half2_rn(acc[mt][nt][0] * s0,
                                                   acc[mt][nt][1] * s0);
                    *(__half2*)(C + (size_t)row0 * K + col) = hv;
                }
                if (row1 < N_NODES) {
                    __half2 hv = __floats2half2_rn(acc[mt][nt][2] * s1,
                                                   acc[mt][nt][3] * s1);
                    *(__half2*)(C + (size_t)row1 * K + col) = hv;
                }
            }
        }
    }
}

// ---------------- fused CSR aggregation + epilogue (fp16 gather) -----------
__device__ __forceinline__ void add8(float acc[8], uint4 raw) {
    float2 f0 = __half22float2(*reinterpret_cast<__half2*>(&raw.x));
    float2 f1 = __half22float2(*reinterpret_cast<__half2*>(&raw.y));
    float2 f2 = __half22float2(*reinterpret_cast<__half2*>(&raw.z));
    float2 f3 = __half22float2(*reinterpret_cast<__half2*>(&raw.w));
    acc[0] += f0.x; acc[1] += f0.y;
    acc[2] += f1.x; acc[3] += f1.y;
    acc[4] += f2.x; acc[5] += f2.y;
    acc[6] += f3.x; acc[7] += f3.y;
}

template<int F, int TPN, bool RELU>
__global__ __launch_bounds__(256)
void agg_fused_k(const __half* __restrict__ h, const int* __restrict__ rowstart,
                 const int* __restrict__ bsum, const int* __restrict__ dege,
                 const int* __restrict__ csrc, const float* __restrict__ dinv,
                 const float* __restrict__ bias, float* __restrict__ z)
{
    __shared__ int sb[32];
    mini_scan_bsum(bsum, sb);

    unsigned t = blockIdx.x * blockDim.x + threadIdx.x;
    unsigned node = t / TPN;
    unsigned col = (t - node * TPN) * 8;
    if (node >= N_NODES) return;

    float acc[8] = {};
    add8(acc, __ldg((const uint4*)(h + (size_t)node * F + col)));   // self loop

    int i   = rowstart[node] + sb[node >> 11];
    int end = i + dege[node];

    for (; i + 4 <= end; i += 4) {
        int p0 = __ldg(&csrc[i + 0]);
        int p1 = __ldg(&csrc[i + 1]);
        int p2 = __ldg(&csrc[i + 2]);
        int p3 = __ldg(&csrc[i + 3]);
        uint4 r0 = __ldg((const uint4*)(h + (size_t)p0 * F + col));
        uint4 r1 = __ldg((const uint4*)(h + (size_t)p1 * F + col));
        uint4 r2 = __ldg((const uint4*)(h + (size_t)p2 * F + col));
        uint4 r3 = __ldg((const uint4*)(h + (size_t)p3 * F + col));
        add8(acc, r0); add8(acc, r1); add8(acc, r2); add8(acc, r3);
    }
    for (; i < end; i++) {
        int p = __ldg(&csrc[i]);
        add8(acc, __ldg((const uint4*)(h + (size_t)p * F + col)));
    }

    float sc = dinv[node];
    float4 b0 = *(const float4*)(bias + col);
    float4 b1 = *(const float4*)(bias + col + 4);
    float4 r0, r1;
    r0.x = fmaf(acc[0], sc, b0.x); r0.y = fmaf(acc[1], sc, b0.y);
    r0.z = fmaf(acc[2], sc, b0.z); r0.w = fmaf(acc[3], sc, b0.w);
    r1.x = fmaf(acc[4], sc, b1.x); r1.y = fmaf(acc[5], sc, b1.y);
    r1.z = fmaf(acc[6], sc, b1.z); r1.w = fmaf(acc[7], sc, b1.w);
    if (RELU) {
        r0.x = fmaxf(r0.x, 0.f); r0.y = fmaxf(r0.y, 0.f);
        r0.z = fmaxf(r0.z, 0.f); r0.w = fmaxf(r0.w, 0.f);
        r1.x = fmaxf(r1.x, 0.f); r1.y = fmaxf(r1.y, 0.f);
        r1.z = fmaxf(r1.z, 0.f); r1.w = fmaxf(r1.w, 0.f);
    }
    *(float4*)(z + (size_t)node * F + col)     = r0;
    *(float4*)(z + (size_t)node * F + col + 4) = r1;
}

// ---------------- launch ---------------------------------------------------
extern "C" void kernel_launch(void* const* d_in, const int* in_sizes, int n_in,
                              void* d_out, int out_size)
{
    const float* x  = (const float*)d_in[0];
    const int*   ei = (const int*)  d_in[1];
    const float* W1 = (const float*)d_in[2];
    const float* b1 = (const float*)d_in[3];
    const float* W2 = (const float*)d_in[4];
    const float* b2 = (const float*)d_in[5];
    const float* W3 = (const float*)d_in[6];
    const float* b3 = (const float*)d_in[7];
    float* out = (float*)d_out;

    const int* src = ei;              // edge_index[0]
    const int* dst = ei + N_EDGES;    // edge_index[1]

    __half* h;
    float *z, *dinv;
    int *dege, *cursor, *rowstart, *csrc, *bsum;
    cudaGetSymbolAddress((void**)&h,        g_h);
    cudaGetSymbolAddress((void**)&z,        g_z);
    cudaGetSymbolAddress((void**)&dinv,     g_dinv);
    cudaGetSymbolAddress((void**)&dege,     g_dege);
    cudaGetSymbolAddress((void**)&cursor,   g_cursor);
    cudaGetSymbolAddress((void**)&rowstart, g_rowstart);
    cudaGetSymbolAddress((void**)&csrc,     g_csrc);
    cudaGetSymbolAddress((void**)&bsum,     g_bsum);

    const int TPB = 256;
    const int edgeBlocks = (N_EDGES + TPB - 1) / TPB;
    const int gemmBlocks = (N_NODES + 127) / 128;
    const int agg64Blocks = ((unsigned)N_NODES * 8 + TPB - 1) / TPB;   // TPN=8
    const int agg40Blocks = ((unsigned)N_NODES * 5 + TPB - 1) / TPB;   // TPN=5

    // ---- CSR build + normalization (4 launches) ----
    cudaMemsetAsync(dege, 0, N_NODES * sizeof(int));
    deg_count_k<<<edgeBlocks, TPB>>>(dst, dege);
    scan1_k    <<<SCAN_NB, SCAN_B>>>(dege, rowstart, bsum, dinv, cursor);
    fill_k     <<<edgeBlocks, TPB>>>(src, dst, rowstart, bsum, cursor, csrc);

    // ---- layer 1: x[50000,128] @ W1[128,64] ----
    gemm_hmma_k<<<gemmBlocks, TPB>>>(x, W1, dinv, h, F_IN, F_HID);
    agg_fused_k<F_HID, 8, true><<<agg64Blocks, TPB>>>(h, rowstart, bsum, dege, csrc, dinv, b1, z);

    // ---- layer 2: z1 @ W2[64,64] ----
    gemm_hmma_k<<<gemmBlocks, TPB>>>(z, W2, dinv, h, F_HID, F_HID);
    agg_fused_k<F_HID, 8, true><<<agg64Blocks, TPB>>>(h, rowstart, bsum, dege, csrc, dinv, b2, z);

    // ---- layer 3: z2 @ W3[64,40] -> d_out ----
    gemm_hmma_k<<<gemmBlocks, TPB>>>(z, W3, dinv, h, F_HID, F_OUT);
    agg_fused_k<F_OUT, 5, false><<<agg40Blocks, TPB>>>(h, rowstart, bsum, dege, csrc, dinv, b3, out);
}